// round 10
// baseline (speedup 1.0000x reference)
#include <cuda_runtime.h>
#include <cuda_fp16.h>
#include <cstdint>

#define NN   10000
#define EE   160000
#define FIN  1152
#define FOUT 288
#define KMAX 7
#define LDT  (KMAX*FIN)   /* 8064 */
#define LDT4 (LDT/4)      /* 2016 */

// ---------------- device scratch ----------------------------------------------
__device__ float4 g_T4[(size_t)KMAX * NN * (FIN/4)];   // fp32 T (recurrence)
#define G_T ((float*)g_T4)
__device__ __half g_Th[(size_t)KMAX * NN * FIN];       // fp16 T (GEMM A)

__device__ int   g_deg[NN];
__device__ float g_dinv[NN];
__device__ int   g_cnt[NN];
__device__ int   g_colptr[NN + 1];
__device__ int   g_cursor[NN];
__device__ int   g_src[EE];
__device__ float g_w[EE];

// fp16 W, transposed to K-major [n][k] per conv, packed
#define WH_OFF0 0
#define WH_OFF1 (4*FIN*FOUT)
#define WH_OFF2 (WH_OFF1 + 5*FIN*FOUT)
#define WH_OFF3 (WH_OFF2 + 6*FIN*FOUT)
#define WH_TOT  (WH_OFF3 + 7*FIN*FOUT)
__device__ __half g_Wh[WH_TOT];

// ---------------- helpers -------------------------------------------------------
__device__ __forceinline__ uint32_t smem_u32(const void* p) {
    return (uint32_t)__cvta_generic_to_shared(p);
}
__device__ __forceinline__ void cp16(uint32_t s, const void* g) {
    asm volatile("cp.async.cg.shared.global [%0], [%1], 16;"
                 :: "r"(s), "l"(__cvta_generic_to_global(g)) : "memory");
}
__device__ __forceinline__ void mma_f16(float* d, const uint32_t* a, const uint32_t* b) {
    asm volatile(
        "mma.sync.aligned.m16n8k16.row.col.f32.f16.f16.f32 "
        "{%0,%1,%2,%3}, {%4,%5,%6,%7}, {%8,%9}, {%0,%1,%2,%3};"
        : "+f"(d[0]), "+f"(d[1]), "+f"(d[2]), "+f"(d[3])
        : "r"(a[0]), "r"(a[1]), "r"(a[2]), "r"(a[3]), "r"(b[0]), "r"(b[1]));
}
__device__ __forceinline__ void ldsm4(uint32_t* r, uint32_t addr) {
    asm volatile("ldmatrix.sync.aligned.m8n8.x4.shared.b16 {%0,%1,%2,%3}, [%4];"
                 : "=r"(r[0]), "=r"(r[1]), "=r"(r[2]), "=r"(r[3]) : "r"(addr));
}
__device__ __forceinline__ void ldsm2(uint32_t* r, uint32_t addr) {
    asm volatile("ldmatrix.sync.aligned.m8n8.x2.shared.b16 {%0,%1}, [%2];"
                 : "=r"(r[0]), "=r"(r[1]) : "r"(addr));
}

// ---------------- setup kernels ------------------------------------------------
__global__ void k_zero() {
    int i = blockIdx.x * blockDim.x + threadIdx.x;
    if (i < NN) { g_deg[i] = 0; g_cnt[i] = 0; g_cursor[i] = 0; }
}
__global__ void k_hist(const int* __restrict__ ei) {
    int e = blockIdx.x * blockDim.x + threadIdx.x;
    if (e < EE) {
        atomicAdd(&g_deg[ei[e]], 1);
        atomicAdd(&g_cnt[ei[EE + e]], 1);
    }
}
__global__ void k_scan() {
    __shared__ int wsum[32];
    const int tid  = threadIdx.x;
    const int lane = tid & 31;
    const int warp = tid >> 5;

    int v[10];
    int s = 0;
#pragma unroll
    for (int i = 0; i < 10; i++) {
        int idx = tid * 10 + i;
        if (idx < NN) {
            v[i] = g_cnt[idx];
            int dg = g_deg[idx];
            g_dinv[idx] = (dg > 0) ? rsqrtf((float)dg) : 0.0f;
        } else v[i] = 0;
        s += v[i];
    }
    int inc = s;
#pragma unroll
    for (int off = 1; off < 32; off <<= 1) {
        int n = __shfl_up_sync(0xFFFFFFFF, inc, off);
        if (lane >= off) inc += n;
    }
    if (lane == 31) wsum[warp] = inc;
    __syncthreads();
    if (warp == 0) {
        int w = wsum[lane];
#pragma unroll
        for (int off = 1; off < 32; off <<= 1) {
            int n = __shfl_up_sync(0xFFFFFFFF, w, off);
            if (lane >= off) w += n;
        }
        wsum[lane] = w;
    }
    __syncthreads();
    int base = (warp > 0 ? wsum[warp - 1] : 0) + inc - s;
#pragma unroll
    for (int i = 0; i < 10; i++) {
        int idx = tid * 10 + i;
        if (idx < NN) g_colptr[idx] = base;
        base += v[i];
    }
    if (tid == 1023) g_colptr[NN] = wsum[31];
}
__global__ void k_scatter(const int* __restrict__ ei) {
    int e = blockIdx.x * blockDim.x + threadIdx.x;
    if (e < EE) {
        int r = ei[e];
        int c = ei[EE + e];
        int p = g_colptr[c] + atomicAdd(&g_cursor[c], 1);
        g_src[p] = r;
        g_w[p]   = -(g_dinv[r] * g_dinv[c]);
    }
}
__global__ void k_copyx(const float* __restrict__ x) {
    const int total = NN * (FIN / 4);
    for (int idx = blockIdx.x * blockDim.x + threadIdx.x; idx < total;
         idx += gridDim.x * blockDim.x) {
        int node = idx / (FIN / 4);
        int r    = idx - node * (FIN / 4);
        float4 v = ((const float4*)x)[idx];
        g_T4[(size_t)node * LDT4 + r] = v;
        const size_t hp = (size_t)node * LDT + (size_t)r * 4;
        *(__half2*)(g_Th + hp)     = __floats2half2_rn(v.x, v.y);
        *(__half2*)(g_Th + hp + 2) = __floats2half2_rn(v.z, v.w);
    }
}
__global__ void k_wt(const float* __restrict__ W0, const float* __restrict__ W1,
                     const float* __restrict__ W2, const float* __restrict__ W3) {
    __shared__ float tile[32][33];
    const int c  = blockIdx.z;
    const int KT = (4 + c) * FIN;
    const int k0 = blockIdx.y * 32;
    if (k0 >= KT) return;
    const float* W = (c == 0) ? W0 : (c == 1) ? W1 : (c == 2) ? W2 : W3;
    const int woff = (c == 0) ? WH_OFF0 : (c == 1) ? WH_OFF1 : (c == 2) ? WH_OFF2 : WH_OFF3;
    const int tx = threadIdx.x, ty = threadIdx.y;
    const int n0 = blockIdx.x * 32;
#pragma unroll
    for (int r = 0; r < 4; r++) {
        int a = ty + 8 * r;
        tile[a][tx] = W[(size_t)(k0 + a) * FOUT + n0 + tx];
    }
    __syncthreads();
#pragma unroll
    for (int r = 0; r < 4; r++) {
        int a = ty + 8 * r;
        g_Wh[(size_t)woff + (size_t)(n0 + a) * KT + k0 + tx] = __float2half_rn(tile[tx][a]);
    }
}

// ---------------- Chebyshev propagation ----------------------------------------
__global__ void k_prop(int kcur) {
    const int node = blockIdx.x;
    const int tid  = threadIdx.x;
    const int beg  = g_colptr[node];
    const int end  = g_colptr[node + 1];

    __shared__ int   ss[64];
    __shared__ float sw[64];

    float4 acc = make_float4(0.f, 0.f, 0.f, 0.f);
    const size_t foff  = (size_t)tid * 4;
    const size_t kprev = (size_t)(kcur - 1) * FIN;

    for (int b0 = beg; b0 < end; b0 += 64) {
        int cnt = min(64, end - b0);
        __syncthreads();
        if (tid < cnt) { ss[tid] = g_src[b0 + tid]; sw[tid] = g_w[b0 + tid]; }
        __syncthreads();
        for (int j = 0; j < cnt; j++) {
            float w = sw[j];
            const float4 v = *(const float4*)(G_T + (size_t)ss[j] * LDT + kprev + foff);
            acc.x += w * v.x; acc.y += w * v.y; acc.z += w * v.z; acc.w += w * v.w;
        }
    }

    const size_t nb = (size_t)node * LDT;
    float4 r;
    if (kcur == 1) {
        r = acc;
    } else {
        const float4 p = *(const float4*)(G_T + nb + (size_t)(kcur - 2) * FIN + foff);
        r.x = 2.f * acc.x - p.x; r.y = 2.f * acc.y - p.y;
        r.z = 2.f * acc.z - p.z; r.w = 2.f * acc.w - p.w;
    }
    const size_t pos = nb + (size_t)kcur * FIN + foff;
    if (kcur < KMAX - 1) *(float4*)(G_T + pos) = r;
    *(__half2*)(g_Th + pos)     = __floats2half2_rn(r.x, r.y);
    *(__half2*)(g_Th + pos + 2) = __floats2half2_rn(r.z, r.w);
}

// ---------------- fp16 mma.sync GEMM (BM=256, 5-stage + frag double buffer) ------
#define BM 256
#define BN 144
#define BK 32
#define ASTRH 40
#define BSTRH 40
#define STAGES 5
#define A_STH (BM*ASTRH)                     /* 10240 halves */
#define B_STH (BN*BSTRH)                     /* 5760 halves */
#define STG_H (A_STH + B_STH)                /* 16000 halves per stage */
#define SMEM_GEMM (STAGES*STG_H*2)           /* 160000 B */

__global__ void __launch_bounds__(256, 1) k_gemm(
    const float* __restrict__ B0, const float* __restrict__ B1,
    const float* __restrict__ B2, const float* __restrict__ B3,
    float* __restrict__ out)
{
    extern __shared__ __align__(16) __half smp[];
    const uint32_t sbase = smem_u32(smp);

    const int c  = 3 - (blockIdx.x & 3);          // heavy convs first
    const int nb = blockIdx.x >> 2;
    const int Kc = 4 + c;
    const int KT = Kc * FIN;
    const int woff = (c == 0) ? WH_OFF0 : (c == 1) ? WH_OFF1 : (c == 2) ? WH_OFF2 : WH_OFF3;
    const __half* W  = g_Wh + woff;
    const float* Bv = (c == 0) ? B0 : (c == 1) ? B1 : (c == 2) ? B2 : B3;

    const int m0  = blockIdx.y * BM;
    const int n0  = nb * BN;
    const int t   = threadIdx.x;
    const int lane = t & 31;
    const int wid  = t >> 5;
    const int warpM = wid >> 1;      // 0..3 (64 rows each)
    const int warpN = wid & 1;       // 0..1 (72 cols each)
    const int lq = lane >> 2;
    const int lr = lane & 3;

    // ldmatrix lane offsets (halves, within a stage)
    const int a_lm = (warpM * 64 + (lane & 7) + (lane & 8)) * ASTRH + ((lane & 16) >> 1);
    const int b_lm = (warpN * 72 + (lane & 7) + ((lane & 16) >> 1)) * BSTRH + (lane & 8);
    const int bs_lm = (warpN * 72 + 64 + (lane & 7)) * BSTRH + (lane & 8);

    // ---- staging coordinates ----
    // A: 256 rows x 32 halves = 1024 x 16B chunks; thread handles rows ar0+64*i
    const int ar0 = t >> 2, ach = (t & 3) * 8;
    const __half* a_src[4];
    uint32_t a_dst[4];
#pragma unroll
    for (int i = 0; i < 4; i++) {
        int row = ar0 + 64 * i;
        int gm = m0 + row; gm = (gm < NN) ? gm : (NN - 1);
        a_src[i] = g_Th + (size_t)gm * LDT + ach;
        a_dst[i] = sbase + (row * ASTRH + ach) * 2;
    }
    // B: 144 rows x 32 halves = 576 chunks; j = t, t+256, (t+512 if t<64)
    int brow[3], bch[3];
#pragma unroll
    for (int i = 0; i < 3; i++) {
        int j = t + 256 * i;
        brow[i] = j >> 2;
        bch[i]  = (j & 3) * 8;
    }
    const bool b3 = (t < 64);
    uint32_t b_dst[3];
    const __half* b_src[3];
#pragma unroll
    for (int i = 0; i < 3; i++) {
        b_dst[i] = sbase + (A_STH + brow[i] * BSTRH + bch[i]) * 2;
        b_src[i] = W + (size_t)(n0 + brow[i]) * KT + bch[i];
    }

    float d[4][9][4];
#pragma unroll
    for (int i = 0; i < 4; i++)
#pragma unroll
        for (int j = 0; j < 9; j++)
#pragma unroll
            for (int q = 0; q < 4; q++) d[i][j][q] = 0.f;

    const int ntiles = KT / BK;

    // prologue: tiles 0..3 into stages 0..3
#pragma unroll
    for (int s = 0; s < STAGES - 1; s++) {
        const int k0 = s * BK;
        const uint32_t so = s * (STG_H * 2);
#pragma unroll
        for (int i = 0; i < 4; i++) cp16(a_dst[i] + so, a_src[i] + k0);
#pragma unroll
        for (int i = 0; i < 2; i++) cp16(b_dst[i] + so, b_src[i] + k0);
        if (b3) cp16(b_dst[2] + so, b_src[2] + k0);
        asm volatile("cp.async.commit_group;" ::: "memory");
    }

    uint32_t af[2][4][4], bf[2][9][2];

    // wait until tiles 0,1 complete; preload frags for (tile0, ks0)
    asm volatile("cp.async.wait_group %0;" :: "n"(STAGES - 3) : "memory");
    __syncthreads();
    {
        const uint32_t sA = sbase;
        const uint32_t sB = sbase + A_STH * 2;
#pragma unroll
        for (int mt = 0; mt < 4; mt++)
            ldsm4(af[0][mt], sA + (a_lm + mt * 16 * ASTRH) * 2);
#pragma unroll
        for (int np = 0; np < 4; np++) {
            uint32_t r4[4];
            ldsm4(r4, sB + (b_lm + np * 16 * BSTRH) * 2);
            bf[0][2 * np][0] = r4[0]; bf[0][2 * np][1] = r4[1];
            bf[0][2 * np + 1][0] = r4[2]; bf[0][2 * np + 1][1] = r4[3];
        }
        ldsm2(bf[0][8], sB + bs_lm * 2);
    }

    for (int it = 0; it < ntiles; ++it) {
        if (it > 0) {
            asm volatile("cp.async.wait_group %0;" :: "n"(STAGES - 3) : "memory");
            __syncthreads();
        }
        {
            const int ld = it + STAGES - 1;
            if (ld < ntiles) {
                const int s = ld % STAGES;
                const int k0 = ld * BK;
                const uint32_t so = s * (STG_H * 2);
#pragma unroll
                for (int i = 0; i < 4; i++) cp16(a_dst[i] + so, a_src[i] + k0);
#pragma unroll
                for (int i = 0; i < 2; i++) cp16(b_dst[i] + so, b_src[i] + k0);
                if (b3) cp16(b_dst[2] + so, b_src[2] + k0);
            }
            asm volatile("cp.async.commit_group;" ::: "memory");
        }

        const int cs = it % STAGES;
        const uint32_t sA = sbase + cs * (STG_H * 2);
        const uint32_t sB = sA + A_STH * 2;

        // ks=0: prefetch (it, ks1) -> buf1, MMA buf0
#pragma unroll
        for (int mt = 0; mt < 4; mt++)
            ldsm4(af[1][mt], sA + (a_lm + mt * 16 * ASTRH + 16) * 2);
#pragma unroll
        for (int np = 0; np < 4; np++) {
            uint32_t r4[4];
            ldsm4(r4, sB + (b_lm + np * 16 * BSTRH + 16) * 2);
            bf[1][2 * np][0] = r4[0]; bf[1][2 * np][1] = r4[1];
            bf[1][2 * np + 1][0] = r4[2]; bf[1][2 * np + 1][1] = r4[3];
        }
        ldsm2(bf[1][8], sB + (bs_lm + 16) * 2);
#pragma unroll
        for (int mt = 0; mt < 4; mt++)
#pragma unroll
            for (int nt = 0; nt < 9; nt++)
                mma_f16(d[mt][nt], af[0][mt], bf[0][nt]);

        // ks=1: prefetch (it+1, ks0) -> buf0 (stage it+1 complete), MMA buf1
        if (it + 1 < ntiles) {
            const int ns = (it + 1) % STAGES;
            const uint32_t nA = sbase + ns * (STG_H * 2);
            const uint32_t nB = nA + A_STH * 2;
#pragma unroll
            for (int mt = 0; mt < 4; mt++)
                ldsm4(af[0][mt], nA + (a_lm + mt * 16 * ASTRH) * 2);
#pragma unroll
            for (int np = 0; np < 4; np++) {
                uint32_t r4[4];
                ldsm4(r4, nB + (b_lm + np * 16 * BSTRH) * 2);
                bf[0][2 * np][0] = r4[0]; bf[0][2 * np][1] = r4[1];
                bf[0][2 * np + 1][0] = r4[2]; bf[0][2 * np + 1][1] = r4[3];
            }
            ldsm2(bf[0][8], nB + bs_lm * 2);
        }
#pragma unroll
        for (int mt = 0; mt < 4; mt++)
#pragma unroll
            for (int nt = 0; nt < 9; nt++)
                mma_f16(d[mt][nt], af[1][mt], bf[1][nt]);
    }

    // epilogue: bias + store
#pragma unroll
    for (int mt = 0; mt < 4; mt++) {
        const int row0 = m0 + warpM * 64 + mt * 16 + lq;
        const int row1 = row0 + 8;
#pragma unroll
        for (int nt = 0; nt < 9; nt++) {
            const int col = warpN * 72 + nt * 8 + lr * 2;
            const float bx = __ldg(&Bv[n0 + col]);
            const float by = __ldg(&Bv[n0 + col + 1]);
            const size_t oc = (size_t)c * FOUT + n0 + col;
            if (row0 < NN) {
                float2 v = make_float2(d[mt][nt][0] + bx, d[mt][nt][1] + by);
                *(float2*)&out[(size_t)row0 * 1152 + oc] = v;
            }
            if (row1 < NN) {
                float2 v = make_float2(d[mt][nt][2] + bx, d[mt][nt][3] + by);
                *(float2*)&out[(size_t)row1 * 1152 + oc] = v;
            }
        }
    }
}

// ---------------- launch --------------------------------------------------------
extern "C" void kernel_launch(void* const* d_in, const int* in_sizes, int n_in,
                              void* d_out, int out_size) {
    const float* x   = (const float*)d_in[0];
    const int*   ei  = (const int*)d_in[1];
    const float* W0  = (const float*)d_in[2];
    const float* B0v = (const float*)d_in[3];
    const float* W1  = (const float*)d_in[4];
    const float* B1v = (const float*)d_in[5];
    const float* W2  = (const float*)d_in[6];
    const float* B2v = (const float*)d_in[7];
    const float* W3  = (const float*)d_in[8];
    const float* B3v = (const float*)d_in[9];
    float* out = (float*)d_out;

    cudaFuncSetAttribute(k_gemm, cudaFuncAttributeMaxDynamicSharedMemorySize, SMEM_GEMM);

    k_zero<<<(NN + 255) / 256, 256>>>();
    k_hist<<<(EE + 255) / 256, 256>>>(ei);
    k_scan<<<1, 1024>>>();
    k_scatter<<<(EE + 255) / 256, 256>>>(ei);
    k_copyx<<<4096, 256>>>(x);

    dim3 tb(32, 8);
    k_wt<<<dim3(9, 7 * 36, 4), tb>>>(W0, W1, W2, W3);

    for (int k = 1; k < KMAX; k++)
        k_prop<<<NN, 288>>>(k);

    dim3 g(4 * (FOUT / BN), (NN + BM - 1) / BM);
    k_gemm<<<g, 256, SMEM_GEMM>>>(B0v, B1v, B2v, B3v, out);
}

// round 11
// speedup vs baseline: 1.0853x; 1.0853x over previous
#include <cuda_runtime.h>
#include <cuda_fp16.h>
#include <cstdint>

#define NN   10000
#define EE   160000
#define FIN  1152
#define FOUT 288
#define NCK  22                 /* total (conv,k) pairs: 4+5+6+7 */
#define NCOL (NCK*FOUT)         /* 6336 */

// ---------------- device scratch ----------------------------------------------
__device__ __half g_Xh[(size_t)NN * FIN];              // fp16 x (GEMM A), 23 MB
__device__ __half g_Wh[(size_t)NCOL * FIN];            // fp16 W K-major [ncol][f], 14.6 MB
__device__ float  g_XW[(size_t)NN * NCOL];             // X@W products, 253 MB
__device__ float  g_P[(size_t)8 * NN * FOUT];          // Clenshaw ping-pong, 92 MB

__device__ int   g_deg[NN];
__device__ float g_dinv[NN];
__device__ int   g_cnt[NN];
__device__ int   g_colptr[NN + 1];
__device__ int   g_cursor[NN];
__device__ int   g_src[EE];
__device__ float g_w[EE];

// ---------------- helpers -------------------------------------------------------
__device__ __forceinline__ uint32_t smem_u32(const void* p) {
    return (uint32_t)__cvta_generic_to_shared(p);
}
__device__ __forceinline__ void cp16(uint32_t s, const void* g) {
    asm volatile("cp.async.cg.shared.global [%0], [%1], 16;"
                 :: "r"(s), "l"(__cvta_generic_to_global(g)) : "memory");
}
__device__ __forceinline__ void mma_f16(float* d, const uint32_t* a, const uint32_t* b) {
    asm volatile(
        "mma.sync.aligned.m16n8k16.row.col.f32.f16.f16.f32 "
        "{%0,%1,%2,%3}, {%4,%5,%6,%7}, {%8,%9}, {%0,%1,%2,%3};"
        : "+f"(d[0]), "+f"(d[1]), "+f"(d[2]), "+f"(d[3])
        : "r"(a[0]), "r"(a[1]), "r"(a[2]), "r"(a[3]), "r"(b[0]), "r"(b[1]));
}
__device__ __forceinline__ void ldsm4(uint32_t* r, uint32_t addr) {
    asm volatile("ldmatrix.sync.aligned.m8n8.x4.shared.b16 {%0,%1,%2,%3}, [%4];"
                 : "=r"(r[0]), "=r"(r[1]), "=r"(r[2]), "=r"(r[3]) : "r"(addr));
}
__device__ __forceinline__ void ldsm2(uint32_t* r, uint32_t addr) {
    asm volatile("ldmatrix.sync.aligned.m8n8.x2.shared.b16 {%0,%1}, [%2];"
                 : "=r"(r[0]), "=r"(r[1]) : "r"(addr));
}

// ---------------- setup kernels ------------------------------------------------
__global__ void k_zero() {
    int i = blockIdx.x * blockDim.x + threadIdx.x;
    if (i < NN) { g_deg[i] = 0; g_cnt[i] = 0; g_cursor[i] = 0; }
}
__global__ void k_hist(const int* __restrict__ ei) {
    int e = blockIdx.x * blockDim.x + threadIdx.x;
    if (e < EE) {
        atomicAdd(&g_deg[ei[e]], 1);
        atomicAdd(&g_cnt[ei[EE + e]], 1);
    }
}
__global__ void k_scan() {
    __shared__ int wsum[32];
    const int tid  = threadIdx.x;
    const int lane = tid & 31;
    const int warp = tid >> 5;

    int v[10];
    int s = 0;
#pragma unroll
    for (int i = 0; i < 10; i++) {
        int idx = tid * 10 + i;
        if (idx < NN) {
            v[i] = g_cnt[idx];
            int dg = g_deg[idx];
            g_dinv[idx] = (dg > 0) ? rsqrtf((float)dg) : 0.0f;
        } else v[i] = 0;
        s += v[i];
    }
    int inc = s;
#pragma unroll
    for (int off = 1; off < 32; off <<= 1) {
        int n = __shfl_up_sync(0xFFFFFFFF, inc, off);
        if (lane >= off) inc += n;
    }
    if (lane == 31) wsum[warp] = inc;
    __syncthreads();
    if (warp == 0) {
        int w = wsum[lane];
#pragma unroll
        for (int off = 1; off < 32; off <<= 1) {
            int n = __shfl_up_sync(0xFFFFFFFF, w, off);
            if (lane >= off) w += n;
        }
        wsum[lane] = w;
    }
    __syncthreads();
    int base = (warp > 0 ? wsum[warp - 1] : 0) + inc - s;
#pragma unroll
    for (int i = 0; i < 10; i++) {
        int idx = tid * 10 + i;
        if (idx < NN) g_colptr[idx] = base;
        base += v[i];
    }
    if (tid == 1023) g_colptr[NN] = wsum[31];
}
__global__ void k_scatter(const int* __restrict__ ei) {
    int e = blockIdx.x * blockDim.x + threadIdx.x;
    if (e < EE) {
        int r = ei[e];
        int c = ei[EE + e];
        int p = g_colptr[c] + atomicAdd(&g_cursor[c], 1);
        g_src[p] = r;
        g_w[p]   = -(g_dinv[r] * g_dinv[c]);
    }
}
// convert x to fp16
__global__ void k_xh(const float* __restrict__ x) {
    const int total = NN * (FIN / 4);
    for (int idx = blockIdx.x * blockDim.x + threadIdx.x; idx < total;
         idx += gridDim.x * blockDim.x) {
        float4 v = ((const float4*)x)[idx];
        __half2* dst = (__half2*)(g_Xh + (size_t)idx * 4);
        dst[0] = __floats2half2_rn(v.x, v.y);
        dst[1] = __floats2half2_rn(v.z, v.w);
    }
}
// W[c][kk][f][o] fp32 -> g_Wh[((offs[c]+kk)*288+o)][f] fp16
__global__ void k_wt(const float* __restrict__ W0, const float* __restrict__ W1,
                     const float* __restrict__ W2, const float* __restrict__ W3) {
    __shared__ float tile[32][33];
    const int z = blockIdx.z;     // 0..21: (c,kk) pair
    int c, kk;
    if (z < 4)      { c = 0; kk = z; }
    else if (z < 9) { c = 1; kk = z - 4; }
    else if (z < 15){ c = 2; kk = z - 9; }
    else            { c = 3; kk = z - 15; }
    const float* W = (c == 0) ? W0 : (c == 1) ? W1 : (c == 2) ? W2 : W3;
    const float* Wk = W + (size_t)kk * FIN * FOUT;     // [f][o]
    const int ncol0 = z * FOUT + blockIdx.x * 32;      // output column base
    const int f0 = blockIdx.y * 32;
    const int tx = threadIdx.x, ty = threadIdx.y;
#pragma unroll
    for (int r = 0; r < 4; r++) {
        int a = ty + 8 * r;       // f index within tile
        tile[a][tx] = Wk[(size_t)(f0 + a) * FOUT + blockIdx.x * 32 + tx];
    }
    __syncthreads();
#pragma unroll
    for (int r = 0; r < 4; r++) {
        int a = ty + 8 * r;       // o index within tile
        g_Wh[(size_t)(ncol0 + a) * FIN + f0 + tx] = __float2half_rn(tile[tx][a]);
    }
}

// ---------------- fp16 mma.sync GEMM: g_XW = Xh @ Wh^T (+bias on k==0 cols) ------
#define BM 128
#define BN 144
#define BK 32
#define ASTRH 40
#define BSTRH 40
#define STAGES 5
#define A_STH (BM*ASTRH)
#define B_STH (BN*BSTRH)
#define STG_H (A_STH + B_STH)
#define SMEM_GEMM (STAGES*STG_H*2)           /* 108800 B */
#define NTILES (FIN/BK)                      /* 36 */

__global__ void __launch_bounds__(128, 2) k_gemm(
    const float* __restrict__ B0, const float* __restrict__ B1,
    const float* __restrict__ B2, const float* __restrict__ B3)
{
    extern __shared__ __align__(16) __half smp[];
    const uint32_t sbase = smem_u32(smp);

    const int m0  = blockIdx.y * BM;
    const int n0  = blockIdx.x * BN;
    // bias: each n-block spans exactly half of one (c,k) product
    const int ck = blockIdx.x >> 1;
    const float* Bv = (ck == 0) ? B0 : (ck == 4) ? B1 : (ck == 9) ? B2
                    : (ck == 15) ? B3 : nullptr;
    const int bcol0 = (blockIdx.x & 1) * BN;

    const int t   = threadIdx.x;
    const int lane = t & 31;
    const int wid  = t >> 5;
    const int warpM = wid >> 1;
    const int warpN = wid & 1;
    const int lq = lane >> 2;
    const int lr = lane & 3;

    const int a_lm = (warpM * 64 + (lane & 7) + (lane & 8)) * ASTRH + ((lane & 16) >> 1);
    const int b_lm = (warpN * 72 + (lane & 7) + ((lane & 16) >> 1)) * BSTRH + (lane & 8);
    const int bs_lm = (warpN * 72 + 64 + (lane & 7)) * BSTRH + (lane & 8);

    const int ar0 = t >> 2, ach = (t & 3) * 8;
    const __half* a_src[4];
    uint32_t a_dst[4];
#pragma unroll
    for (int i = 0; i < 4; i++) {
        int row = ar0 + 32 * i;
        int gm = m0 + row; gm = (gm < NN) ? gm : (NN - 1);
        a_src[i] = g_Xh + (size_t)gm * FIN + ach;
        a_dst[i] = sbase + (row * ASTRH + ach) * 2;
    }
    int brow[5], bch[5];
#pragma unroll
    for (int i = 0; i < 5; i++) {
        int j = t + 128 * i;
        brow[i] = j >> 2;
        bch[i]  = (j & 3) * 8;
    }
    const bool b5 = (t < 64);
    uint32_t b_dst[5];
    const __half* b_src[5];
#pragma unroll
    for (int i = 0; i < 5; i++) {
        b_dst[i] = sbase + (A_STH + brow[i] * BSTRH + bch[i]) * 2;
        b_src[i] = g_Wh + (size_t)(n0 + brow[i]) * FIN + bch[i];
    }

    float d[4][9][4];
#pragma unroll
    for (int i = 0; i < 4; i++)
#pragma unroll
        for (int j = 0; j < 9; j++)
#pragma unroll
            for (int q = 0; q < 4; q++) d[i][j][q] = 0.f;

    // prologue: tiles 0..3
#pragma unroll
    for (int s = 0; s < STAGES - 1; s++) {
        const int k0 = s * BK;
        const uint32_t so = s * (STG_H * 2);
#pragma unroll
        for (int i = 0; i < 4; i++) cp16(a_dst[i] + so, a_src[i] + k0);
#pragma unroll
        for (int i = 0; i < 4; i++) cp16(b_dst[i] + so, b_src[i] + k0);
        if (b5) cp16(b_dst[4] + so, b_src[4] + k0);
        asm volatile("cp.async.commit_group;" ::: "memory");
    }

    uint32_t af[2][4][4], bf[2][9][2];

    asm volatile("cp.async.wait_group %0;" :: "n"(STAGES - 3) : "memory");
    __syncthreads();
    {
        const uint32_t sA = sbase;
        const uint32_t sB = sbase + A_STH * 2;
#pragma unroll
        for (int mt = 0; mt < 4; mt++)
            ldsm4(af[0][mt], sA + (a_lm + mt * 16 * ASTRH) * 2);
#pragma unroll
        for (int np = 0; np < 4; np++) {
            uint32_t r4[4];
            ldsm4(r4, sB + (b_lm + np * 16 * BSTRH) * 2);
            bf[0][2 * np][0] = r4[0]; bf[0][2 * np][1] = r4[1];
            bf[0][2 * np + 1][0] = r4[2]; bf[0][2 * np + 1][1] = r4[3];
        }
        ldsm2(bf[0][8], sB + bs_lm * 2);
    }

    for (int it = 0; it < NTILES; ++it) {
        if (it > 0) {
            asm volatile("cp.async.wait_group %0;" :: "n"(STAGES - 3) : "memory");
            __syncthreads();
        }
        {
            const int ld = it + STAGES - 1;
            if (ld < NTILES) {
                const int s = ld % STAGES;
                const int k0 = ld * BK;
                const uint32_t so = s * (STG_H * 2);
#pragma unroll
                for (int i = 0; i < 4; i++) cp16(a_dst[i] + so, a_src[i] + k0);
#pragma unroll
                for (int i = 0; i < 4; i++) cp16(b_dst[i] + so, b_src[i] + k0);
                if (b5) cp16(b_dst[4] + so, b_src[4] + k0);
            }
            asm volatile("cp.async.commit_group;" ::: "memory");
        }

        const int cs = it % STAGES;
        const uint32_t sA = sbase + cs * (STG_H * 2);
        const uint32_t sB = sA + A_STH * 2;

#pragma unroll
        for (int mt = 0; mt < 4; mt++)
            ldsm4(af[1][mt], sA + (a_lm + mt * 16 * ASTRH + 16) * 2);
#pragma unroll
        for (int np = 0; np < 4; np++) {
            uint32_t r4[4];
            ldsm4(r4, sB + (b_lm + np * 16 * BSTRH + 16) * 2);
            bf[1][2 * np][0] = r4[0]; bf[1][2 * np][1] = r4[1];
            bf[1][2 * np + 1][0] = r4[2]; bf[1][2 * np + 1][1] = r4[3];
        }
        ldsm2(bf[1][8], sB + (bs_lm + 16) * 2);
#pragma unroll
        for (int mt = 0; mt < 4; mt++)
#pragma unroll
            for (int nt = 0; nt < 9; nt++)
                mma_f16(d[mt][nt], af[0][mt], bf[0][nt]);

        if (it + 1 < NTILES) {
            const int ns = (it + 1) % STAGES;
            const uint32_t nA = sbase + ns * (STG_H * 2);
            const uint32_t nB = nA + A_STH * 2;
#pragma unroll
            for (int mt = 0; mt < 4; mt++)
                ldsm4(af[0][mt], nA + (a_lm + mt * 16 * ASTRH) * 2);
#pragma unroll
            for (int np = 0; np < 4; np++) {
                uint32_t r4[4];
                ldsm4(r4, nB + (b_lm + np * 16 * BSTRH) * 2);
                bf[0][2 * np][0] = r4[0]; bf[0][2 * np][1] = r4[1];
                bf[0][2 * np + 1][0] = r4[2]; bf[0][2 * np + 1][1] = r4[3];
            }
            ldsm2(bf[0][8], nB + bs_lm * 2);
        }
#pragma unroll
        for (int mt = 0; mt < 4; mt++)
#pragma unroll
            for (int nt = 0; nt < 9; nt++)
                mma_f16(d[mt][nt], af[1][mt], bf[1][nt]);
    }

    // epilogue -> g_XW (+bias on k==0 product columns)
#pragma unroll
    for (int mt = 0; mt < 4; mt++) {
        const int row0 = m0 + warpM * 64 + mt * 16 + lq;
        const int row1 = row0 + 8;
#pragma unroll
        for (int nt = 0; nt < 9; nt++) {
            const int col = warpN * 72 + nt * 8 + lr * 2;
            float bx = 0.f, by = 0.f;
            if (Bv) { bx = __ldg(&Bv[bcol0 + col]); by = __ldg(&Bv[bcol0 + col + 1]); }
            if (row0 < NN) {
                float2 v = make_float2(d[mt][nt][0] + bx, d[mt][nt][1] + by);
                *(float2*)&g_XW[(size_t)row0 * NCOL + n0 + col] = v;
            }
            if (row1 < NN) {
                float2 v = make_float2(d[mt][nt][2] + bx, d[mt][nt][3] + by);
                *(float2*)&g_XW[(size_t)row1 * NCOL + n0 + col] = v;
            }
        }
    }
}

// ---------------- Clenshaw step kernel -------------------------------------------
struct CleArgs {
    const float* src[4]; int sstr[4];
    const float* xw[4];                        // stride NCOL
    const float* prv[4]; int pstr[4];          // null -> zero
    float*       dst[4]; int dstr[4];
    float coef[4];
};

template <int NACT>
__global__ void __launch_bounds__(FOUT) k_cle(CleArgs A) {
    const int node = blockIdx.x;
    const int tid  = threadIdx.x;              // 288
    const int beg  = g_colptr[node];
    const int end  = g_colptr[node + 1];

    __shared__ int   ss[64];
    __shared__ float sw[64];

    float acc[NACT];
#pragma unroll
    for (int a = 0; a < NACT; a++) acc[a] = 0.f;

    for (int b0 = beg; b0 < end; b0 += 64) {
        int cnt = min(64, end - b0);
        __syncthreads();
        if (tid < cnt) { ss[tid] = g_src[b0 + tid]; sw[tid] = g_w[b0 + tid]; }
        __syncthreads();
        for (int j = 0; j < cnt; j++) {
            const float w = sw[j];
            const size_t nb = (size_t)ss[j];
#pragma unroll
            for (int a = 0; a < NACT; a++)
                acc[a] += w * A.src[a][nb * A.sstr[a] + tid];
        }
    }

#pragma unroll
    for (int a = 0; a < NACT; a++) {
        float v = A.xw[a][(size_t)node * NCOL + tid] + A.coef[a] * acc[a];
        if (A.prv[a]) v -= A.prv[a][(size_t)node * A.pstr[a] + tid];
        A.dst[a][(size_t)node * A.dstr[a] + tid] = v;
    }
}

// ---------------- launch --------------------------------------------------------
extern "C" void kernel_launch(void* const* d_in, const int* in_sizes, int n_in,
                              void* d_out, int out_size) {
    const float* x   = (const float*)d_in[0];
    const int*   ei  = (const int*)d_in[1];
    const float* W0  = (const float*)d_in[2];
    const float* B0v = (const float*)d_in[3];
    const float* W1  = (const float*)d_in[4];
    const float* B1v = (const float*)d_in[5];
    const float* W2  = (const float*)d_in[6];
    const float* B2v = (const float*)d_in[7];
    const float* W3  = (const float*)d_in[8];
    const float* B3v = (const float*)d_in[9];
    float* out = (float*)d_out;

    static float* pXW = nullptr;
    static float* pP  = nullptr;
    if (!pXW) {
        void* p;
        cudaGetSymbolAddress(&p, g_XW); pXW = (float*)p;
        cudaGetSymbolAddress(&p, g_P);  pP  = (float*)p;
        cudaFuncSetAttribute(k_gemm, cudaFuncAttributeMaxDynamicSharedMemorySize, SMEM_GEMM);
    }
    static const int offs[4] = {0, 4, 9, 15};
    auto XWcol = [&](int c, int kk) { return pXW + (size_t)(offs[c] + kk) * FOUT; };
    auto Pbuf  = [&](int c, int par) { return pP + (size_t)(c * 2 + par) * NN * FOUT; };

    k_zero<<<(NN + 255) / 256, 256>>>();
    k_hist<<<(EE + 255) / 256, 256>>>(ei);
    k_scan<<<1, 1024>>>();
    k_scatter<<<(EE + 255) / 256, 256>>>(ei);
    k_xh<<<2048, 256>>>(x);

    dim3 tb(32, 8);
    k_wt<<<dim3(9, 36, NCK), tb>>>(W0, W1, W2, W3);

    dim3 gg(NCOL / BN, (NN + BM - 1) / BM);   // 44 x 79
    k_gemm<<<gg, 128, SMEM_GEMM>>>(B0v, B1v, B2v, B3v);

    // Clenshaw: conv c (K=4+c) starts at t = 3-c; all finals land at t = 5
    for (int t = 0; t < 6; t++) {
        CleArgs A;
        int nact = 0;
        for (int c = 3; c >= 0; c--) {            // heavier chains first in slot order
            const int ts = 3 - c;
            if (t < ts) continue;
            const int K = 4 + c;
            const int s = t - ts;
            const int k = K - 2 - s;
            const int a = nact++;
            if (s == 0) { A.src[a] = XWcol(c, K - 1); A.sstr[a] = NCOL; }
            else        { A.src[a] = Pbuf(c, (s - 1) & 1); A.sstr[a] = FOUT; }
            if (s == 0)      { A.prv[a] = nullptr;            A.pstr[a] = 0; }
            else if (s == 1) { A.prv[a] = XWcol(c, K - 1);    A.pstr[a] = NCOL; }
            else             { A.prv[a] = Pbuf(c, s & 1);     A.pstr[a] = FOUT; }
            if (s == K - 2) { A.dst[a] = out + c * FOUT; A.dstr[a] = 4 * FOUT; A.coef[a] = 1.f; }
            else            { A.dst[a] = Pbuf(c, s & 1); A.dstr[a] = FOUT;     A.coef[a] = 2.f; }
            A.xw[a] = XWcol(c, k);
        }
        switch (nact) {
            case 1: k_cle<1><<<NN, FOUT>>>(A); break;
            case 2: k_cle<2><<<NN, FOUT>>>(A); break;
            case 3: k_cle<3><<<NN, FOUT>>>(A); break;
            default: k_cle<4><<<NN, FOUT>>>(A); break;
        }
    }
}

// round 12
// speedup vs baseline: 1.2455x; 1.1476x over previous
#include <cuda_runtime.h>
#include <cuda_fp16.h>
#include <cstdint>

#define NN   10000
#define EE   160000
#define FIN  1152
#define FOUT 288
#define NCK  22                 /* total (conv,k) pairs: 4+5+6+7 */
#define NCOL (NCK*FOUT)         /* 6336 */

// ---------------- device scratch ----------------------------------------------
__device__ __half g_Xh[(size_t)NN * FIN];              // fp16 x (GEMM A)
__device__ __half g_Wh[(size_t)NCOL * FIN];            // fp16 W K-major [ncol][f]
__device__ float  g_XW[(size_t)NN * NCOL];             // X@W products
__device__ float  g_P[(size_t)8 * NN * FOUT];          // Clenshaw ping-pong

__device__ int   g_deg[NN];
__device__ float g_dinv[NN];
__device__ int   g_cnt[NN];
__device__ int   g_colptr[NN + 1];
__device__ int   g_cursor[NN];
__device__ int   g_src[EE];
__device__ float g_w[EE];

// ---------------- helpers -------------------------------------------------------
__device__ __forceinline__ uint32_t smem_u32(const void* p) {
    return (uint32_t)__cvta_generic_to_shared(p);
}
__device__ __forceinline__ void cp16(uint32_t s, const void* g) {
    asm volatile("cp.async.cg.shared.global [%0], [%1], 16;"
                 :: "r"(s), "l"(__cvta_generic_to_global(g)) : "memory");
}
__device__ __forceinline__ void mma_f16(float* d, const uint32_t* a, const uint32_t* b) {
    asm volatile(
        "mma.sync.aligned.m16n8k16.row.col.f32.f16.f16.f32 "
        "{%0,%1,%2,%3}, {%4,%5,%6,%7}, {%8,%9}, {%0,%1,%2,%3};"
        : "+f"(d[0]), "+f"(d[1]), "+f"(d[2]), "+f"(d[3])
        : "r"(a[0]), "r"(a[1]), "r"(a[2]), "r"(a[3]), "r"(b[0]), "r"(b[1]));
}
__device__ __forceinline__ void ldsm4(uint32_t* r, uint32_t addr) {
    asm volatile("ldmatrix.sync.aligned.m8n8.x4.shared.b16 {%0,%1,%2,%3}, [%4];"
                 : "=r"(r[0]), "=r"(r[1]), "=r"(r[2]), "=r"(r[3]) : "r"(addr));
}
__device__ __forceinline__ void ldsm2(uint32_t* r, uint32_t addr) {
    asm volatile("ldmatrix.sync.aligned.m8n8.x2.shared.b16 {%0,%1}, [%2];"
                 : "=r"(r[0]), "=r"(r[1]) : "r"(addr));
}

// ---------------- setup kernels ------------------------------------------------
__global__ void k_zero() {
    int i = blockIdx.x * blockDim.x + threadIdx.x;
    if (i < NN) { g_deg[i] = 0; g_cnt[i] = 0; g_cursor[i] = 0; }
}
__global__ void k_hist(const int* __restrict__ ei) {
    int e = blockIdx.x * blockDim.x + threadIdx.x;
    if (e < EE) {
        atomicAdd(&g_deg[ei[e]], 1);
        atomicAdd(&g_cnt[ei[EE + e]], 1);
    }
}
__global__ void k_scan() {
    __shared__ int wsum[32];
    const int tid  = threadIdx.x;
    const int lane = tid & 31;
    const int warp = tid >> 5;

    int v[10];
    int s = 0;
#pragma unroll
    for (int i = 0; i < 10; i++) {
        int idx = tid * 10 + i;
        if (idx < NN) {
            v[i] = g_cnt[idx];
            int dg = g_deg[idx];
            g_dinv[idx] = (dg > 0) ? rsqrtf((float)dg) : 0.0f;
        } else v[i] = 0;
        s += v[i];
    }
    int inc = s;
#pragma unroll
    for (int off = 1; off < 32; off <<= 1) {
        int n = __shfl_up_sync(0xFFFFFFFF, inc, off);
        if (lane >= off) inc += n;
    }
    if (lane == 31) wsum[warp] = inc;
    __syncthreads();
    if (warp == 0) {
        int w = wsum[lane];
#pragma unroll
        for (int off = 1; off < 32; off <<= 1) {
            int n = __shfl_up_sync(0xFFFFFFFF, w, off);
            if (lane >= off) w += n;
        }
        wsum[lane] = w;
    }
    __syncthreads();
    int base = (warp > 0 ? wsum[warp - 1] : 0) + inc - s;
#pragma unroll
    for (int i = 0; i < 10; i++) {
        int idx = tid * 10 + i;
        if (idx < NN) g_colptr[idx] = base;
        base += v[i];
    }
    if (tid == 1023) g_colptr[NN] = wsum[31];
}
__global__ void k_scatter(const int* __restrict__ ei) {
    int e = blockIdx.x * blockDim.x + threadIdx.x;
    if (e < EE) {
        int r = ei[e];
        int c = ei[EE + e];
        int p = g_colptr[c] + atomicAdd(&g_cursor[c], 1);
        g_src[p] = r;
        g_w[p]   = -(g_dinv[r] * g_dinv[c]);
    }
}
__global__ void k_xh(const float* __restrict__ x) {
    const int total = NN * (FIN / 4);
    for (int idx = blockIdx.x * blockDim.x + threadIdx.x; idx < total;
         idx += gridDim.x * blockDim.x) {
        float4 v = ((const float4*)x)[idx];
        __half2* dst = (__half2*)(g_Xh + (size_t)idx * 4);
        dst[0] = __floats2half2_rn(v.x, v.y);
        dst[1] = __floats2half2_rn(v.z, v.w);
    }
}
// W[c][kk][f][o] fp32 -> g_Wh[((offs[c]+kk)*288+o)][f] fp16
__global__ void k_wt(const float* __restrict__ W0, const float* __restrict__ W1,
                     const float* __restrict__ W2, const float* __restrict__ W3) {
    __shared__ float tile[32][33];
    const int z = blockIdx.z;     // 0..21: (c,kk) pair
    int c, kk;
    if (z < 4)      { c = 0; kk = z; }
    else if (z < 9) { c = 1; kk = z - 4; }
    else if (z < 15){ c = 2; kk = z - 9; }
    else            { c = 3; kk = z - 15; }
    const float* W = (c == 0) ? W0 : (c == 1) ? W1 : (c == 2) ? W2 : W3;
    const float* Wk = W + (size_t)kk * FIN * FOUT;
    const int ncol0 = z * FOUT + blockIdx.x * 32;
    const int f0 = blockIdx.y * 32;
    const int tx = threadIdx.x, ty = threadIdx.y;
#pragma unroll
    for (int r = 0; r < 4; r++) {
        int a = ty + 8 * r;
        tile[a][tx] = Wk[(size_t)(f0 + a) * FOUT + blockIdx.x * 32 + tx];
    }
    __syncthreads();
#pragma unroll
    for (int r = 0; r < 4; r++) {
        int a = ty + 8 * r;
        g_Wh[(size_t)(ncol0 + a) * FIN + f0 + tx] = __float2half_rn(tile[tx][a]);
    }
}

// ---------------- fp16 mma.sync GEMM: g_XW = Xh @ Wh^T (+bias on k==0 cols) ------
#define BM 128
#define BN 144
#define BK 32
#define ASTRH 40
#define BSTRH 40
#define STAGES 5
#define A_STH (BM*ASTRH)
#define B_STH (BN*BSTRH)
#define STG_H (A_STH + B_STH)
#define SMEM_GEMM (STAGES*STG_H*2)           /* 108800 B */
#define NTILES (FIN/BK)                      /* 36 */

__global__ void __launch_bounds__(128, 2) k_gemm(
    const float* __restrict__ B0, const float* __restrict__ B1,
    const float* __restrict__ B2, const float* __restrict__ B3)
{
    extern __shared__ __align__(16) __half smp[];
    const uint32_t sbase = smem_u32(smp);

    const int m0  = blockIdx.y * BM;
    const int n0  = blockIdx.x * BN;
    const int ck = blockIdx.x >> 1;
    const float* Bv = (ck == 0) ? B0 : (ck == 4) ? B1 : (ck == 9) ? B2
                    : (ck == 15) ? B3 : nullptr;
    const int bcol0 = (blockIdx.x & 1) * BN;

    const int t   = threadIdx.x;
    const int lane = t & 31;
    const int wid  = t >> 5;
    const int warpM = wid >> 1;
    const int warpN = wid & 1;
    const int lq = lane >> 2;
    const int lr = lane & 3;

    const int a_lm = (warpM * 64 + (lane & 7) + (lane & 8)) * ASTRH + ((lane & 16) >> 1);
    const int b_lm = (warpN * 72 + (lane & 7) + ((lane & 16) >> 1)) * BSTRH + (lane & 8);
    const int bs_lm = (warpN * 72 + 64 + (lane & 7)) * BSTRH + (lane & 8);

    const int ar0 = t >> 2, ach = (t & 3) * 8;
    const __half* a_src[4];
    uint32_t a_dst[4];
#pragma unroll
    for (int i = 0; i < 4; i++) {
        int row = ar0 + 32 * i;
        int gm = m0 + row; gm = (gm < NN) ? gm : (NN - 1);
        a_src[i] = g_Xh + (size_t)gm * FIN + ach;
        a_dst[i] = sbase + (row * ASTRH + ach) * 2;
    }
    int brow[5], bch[5];
#pragma unroll
    for (int i = 0; i < 5; i++) {
        int j = t + 128 * i;
        brow[i] = j >> 2;
        bch[i]  = (j & 3) * 8;
    }
    const bool b5 = (t < 64);
    uint32_t b_dst[5];
    const __half* b_src[5];
#pragma unroll
    for (int i = 0; i < 5; i++) {
        b_dst[i] = sbase + (A_STH + brow[i] * BSTRH + bch[i]) * 2;
        b_src[i] = g_Wh + (size_t)(n0 + brow[i]) * FIN + bch[i];
    }

    float d[4][9][4];
#pragma unroll
    for (int i = 0; i < 4; i++)
#pragma unroll
        for (int j = 0; j < 9; j++)
#pragma unroll
            for (int q = 0; q < 4; q++) d[i][j][q] = 0.f;

#pragma unroll
    for (int s = 0; s < STAGES - 1; s++) {
        const int k0 = s * BK;
        const uint32_t so = s * (STG_H * 2);
#pragma unroll
        for (int i = 0; i < 4; i++) cp16(a_dst[i] + so, a_src[i] + k0);
#pragma unroll
        for (int i = 0; i < 4; i++) cp16(b_dst[i] + so, b_src[i] + k0);
        if (b5) cp16(b_dst[4] + so, b_src[4] + k0);
        asm volatile("cp.async.commit_group;" ::: "memory");
    }

    uint32_t af[2][4][4], bf[2][9][2];

    asm volatile("cp.async.wait_group %0;" :: "n"(STAGES - 3) : "memory");
    __syncthreads();
    {
        const uint32_t sA = sbase;
        const uint32_t sB = sbase + A_STH * 2;
#pragma unroll
        for (int mt = 0; mt < 4; mt++)
            ldsm4(af[0][mt], sA + (a_lm + mt * 16 * ASTRH) * 2);
#pragma unroll
        for (int np = 0; np < 4; np++) {
            uint32_t r4[4];
            ldsm4(r4, sB + (b_lm + np * 16 * BSTRH) * 2);
            bf[0][2 * np][0] = r4[0]; bf[0][2 * np][1] = r4[1];
            bf[0][2 * np + 1][0] = r4[2]; bf[0][2 * np + 1][1] = r4[3];
        }
        ldsm2(bf[0][8], sB + bs_lm * 2);
    }

    for (int it = 0; it < NTILES; ++it) {
        if (it > 0) {
            asm volatile("cp.async.wait_group %0;" :: "n"(STAGES - 3) : "memory");
            __syncthreads();
        }
        {
            const int ld = it + STAGES - 1;
            if (ld < NTILES) {
                const int s = ld % STAGES;
                const int k0 = ld * BK;
                const uint32_t so = s * (STG_H * 2);
#pragma unroll
                for (int i = 0; i < 4; i++) cp16(a_dst[i] + so, a_src[i] + k0);
#pragma unroll
                for (int i = 0; i < 4; i++) cp16(b_dst[i] + so, b_src[i] + k0);
                if (b5) cp16(b_dst[4] + so, b_src[4] + k0);
            }
            asm volatile("cp.async.commit_group;" ::: "memory");
        }

        const int cs = it % STAGES;
        const uint32_t sA = sbase + cs * (STG_H * 2);
        const uint32_t sB = sA + A_STH * 2;

#pragma unroll
        for (int mt = 0; mt < 4; mt++)
            ldsm4(af[1][mt], sA + (a_lm + mt * 16 * ASTRH + 16) * 2);
#pragma unroll
        for (int np = 0; np < 4; np++) {
            uint32_t r4[4];
            ldsm4(r4, sB + (b_lm + np * 16 * BSTRH + 16) * 2);
            bf[1][2 * np][0] = r4[0]; bf[1][2 * np][1] = r4[1];
            bf[1][2 * np + 1][0] = r4[2]; bf[1][2 * np + 1][1] = r4[3];
        }
        ldsm2(bf[1][8], sB + (bs_lm + 16) * 2);
#pragma unroll
        for (int mt = 0; mt < 4; mt++)
#pragma unroll
            for (int nt = 0; nt < 9; nt++)
                mma_f16(d[mt][nt], af[0][mt], bf[0][nt]);

        if (it + 1 < NTILES) {
            const int ns = (it + 1) % STAGES;
            const uint32_t nA = sbase + ns * (STG_H * 2);
            const uint32_t nB = nA + A_STH * 2;
#pragma unroll
            for (int mt = 0; mt < 4; mt++)
                ldsm4(af[0][mt], nA + (a_lm + mt * 16 * ASTRH) * 2);
#pragma unroll
            for (int np = 0; np < 4; np++) {
                uint32_t r4[4];
                ldsm4(r4, nB + (b_lm + np * 16 * BSTRH) * 2);
                bf[0][2 * np][0] = r4[0]; bf[0][2 * np][1] = r4[1];
                bf[0][2 * np + 1][0] = r4[2]; bf[0][2 * np + 1][1] = r4[3];
            }
            ldsm2(bf[0][8], nB + bs_lm * 2);
        }
#pragma unroll
        for (int mt = 0; mt < 4; mt++)
#pragma unroll
            for (int nt = 0; nt < 9; nt++)
                mma_f16(d[mt][nt], af[1][mt], bf[1][nt]);
    }

#pragma unroll
    for (int mt = 0; mt < 4; mt++) {
        const int row0 = m0 + warpM * 64 + mt * 16 + lq;
        const int row1 = row0 + 8;
#pragma unroll
        for (int nt = 0; nt < 9; nt++) {
            const int col = warpN * 72 + nt * 8 + lr * 2;
            float bx = 0.f, by = 0.f;
            if (Bv) { bx = __ldg(&Bv[bcol0 + col]); by = __ldg(&Bv[bcol0 + col + 1]); }
            if (row0 < NN) {
                float2 v = make_float2(d[mt][nt][0] + bx, d[mt][nt][1] + by);
                *(float2*)&g_XW[(size_t)row0 * NCOL + n0 + col] = v;
            }
            if (row1 < NN) {
                float2 v = make_float2(d[mt][nt][2] + bx, d[mt][nt][3] + by);
                *(float2*)&g_XW[(size_t)row1 * NCOL + n0 + col] = v;
            }
        }
    }
}

// ---------------- Clenshaw step kernel (float4 per thread) -----------------------
struct CleArgs {
    const float* src[4]; int sstr4[4];         // strides in float4 units
    const float* xw[4];                        // stride NCOL
    const float* prv[4]; int pstr4[4];         // null -> zero
    float*       dst[4]; int dstr4[4];
    float coef[4];
};

// 288 threads: thread t -> (chain a = t/72, col4 = t%72); one float4/thread/edge.
template <int NACT>
__global__ void __launch_bounds__(288) k_cle(CleArgs A) {
    const int node = blockIdx.x;
    const int tid  = threadIdx.x;
    const int a    = tid / 72;
    const int c4   = tid % 72;
    const bool act = (a < NACT);

    const int beg  = g_colptr[node];
    const int end  = g_colptr[node + 1];

    __shared__ int   ss[64];
    __shared__ float sw[64];

    const float4* srcp = act ? ((const float4*)A.src[a]) + c4 : nullptr;
    const int     sst4 = act ? A.sstr4[a] : 0;

    float4 acc = make_float4(0.f, 0.f, 0.f, 0.f);

    for (int b0 = beg; b0 < end; b0 += 64) {
        int cnt = min(64, end - b0);
        __syncthreads();
        if (tid < cnt) { ss[tid] = g_src[b0 + tid]; sw[tid] = g_w[b0 + tid]; }
        __syncthreads();
        if (act) {
            for (int j = 0; j < cnt; j++) {
                const float w = sw[j];
                const float4 v = srcp[(size_t)ss[j] * sst4];
                acc.x += w * v.x; acc.y += w * v.y;
                acc.z += w * v.z; acc.w += w * v.w;
            }
        }
    }

    if (act) {
        const float  cf = A.coef[a];
        const float4 x4 = ((const float4*)A.xw[a])[(size_t)node * (NCOL / 4) + c4];
        float4 v;
        v.x = x4.x + cf * acc.x; v.y = x4.y + cf * acc.y;
        v.z = x4.z + cf * acc.z; v.w = x4.w + cf * acc.w;
        if (A.prv[a]) {
            const float4 p = ((const float4*)A.prv[a])[(size_t)node * A.pstr4[a] + c4];
            v.x -= p.x; v.y -= p.y; v.z -= p.z; v.w -= p.w;
        }
        ((float4*)A.dst[a])[(size_t)node * A.dstr4[a] + c4] = v;
    }
}

// ---------------- launch --------------------------------------------------------
extern "C" void kernel_launch(void* const* d_in, const int* in_sizes, int n_in,
                              void* d_out, int out_size) {
    const float* x   = (const float*)d_in[0];
    const int*   ei  = (const int*)d_in[1];
    const float* W0  = (const float*)d_in[2];
    const float* B0v = (const float*)d_in[3];
    const float* W1  = (const float*)d_in[4];
    const float* B1v = (const float*)d_in[5];
    const float* W2  = (const float*)d_in[6];
    const float* B2v = (const float*)d_in[7];
    const float* W3  = (const float*)d_in[8];
    const float* B3v = (const float*)d_in[9];
    float* out = (float*)d_out;

    static float* pXW = nullptr;
    static float* pP  = nullptr;
    static cudaStream_t s1 = nullptr;
    static cudaEvent_t evA = nullptr, evB = nullptr;
    if (!pXW) {
        void* p;
        cudaGetSymbolAddress(&p, g_XW); pXW = (float*)p;
        cudaGetSymbolAddress(&p, g_P);  pP  = (float*)p;
        cudaFuncSetAttribute(k_gemm, cudaFuncAttributeMaxDynamicSharedMemorySize, SMEM_GEMM);
        cudaStreamCreateWithFlags(&s1, cudaStreamNonBlocking);
        cudaEventCreateWithFlags(&evA, cudaEventDisableTiming);
        cudaEventCreateWithFlags(&evB, cudaEventDisableTiming);
    }
    static const int offs[4] = {0, 4, 9, 15};
    auto XWcol = [&](int c, int kk) { return pXW + (size_t)(offs[c] + kk) * FOUT; };
    auto Pbuf  = [&](int c, int par) { return pP + (size_t)(c * 2 + par) * NN * FOUT; };

    // fork: edge preprocessing on s1 (tiny), concurrent with conversion + GEMM
    cudaEventRecord(evA, 0);
    cudaStreamWaitEvent(s1, evA, 0);
    k_zero<<<(NN + 255) / 256, 256, 0, s1>>>();
    k_hist<<<(EE + 255) / 256, 256, 0, s1>>>(ei);
    k_scan<<<1, 1024, 0, s1>>>();
    k_scatter<<<(EE + 255) / 256, 256, 0, s1>>>(ei);
    cudaEventRecord(evB, s1);

    k_xh<<<2048, 256>>>(x);
    dim3 tb(32, 8);
    k_wt<<<dim3(9, 36, NCK), tb>>>(W0, W1, W2, W3);

    dim3 gg(NCOL / BN, (NN + BM - 1) / BM);
    k_gemm<<<gg, 128, SMEM_GEMM>>>(B0v, B1v, B2v, B3v);

    // join: Clenshaw needs both GEMM results and edge structure
    cudaStreamWaitEvent(0, evB, 0);

    // Clenshaw: conv c (K=4+c) starts at t = 3-c; all finals land at t = 5
    for (int t = 0; t < 6; t++) {
        CleArgs A;
        int nact = 0;
        for (int c = 3; c >= 0; c--) {
            const int ts = 3 - c;
            if (t < ts) continue;
            const int K = 4 + c;
            const int s = t - ts;
            const int k = K - 2 - s;
            const int a = nact++;
            if (s == 0) { A.src[a] = XWcol(c, K - 1); A.sstr4[a] = NCOL / 4; }
            else        { A.src[a] = Pbuf(c, (s - 1) & 1); A.sstr4[a] = FOUT / 4; }
            if (s == 0)      { A.prv[a] = nullptr;          A.pstr4[a] = 0; }
            else if (s == 1) { A.prv[a] = XWcol(c, K - 1);  A.pstr4[a] = NCOL / 4; }
            else             { A.prv[a] = Pbuf(c, s & 1);   A.pstr4[a] = FOUT / 4; }
            if (s == K - 2) { A.dst[a] = out + c * FOUT; A.dstr4[a] = (4 * FOUT) / 4; A.coef[a] = 1.f; }
            else            { A.dst[a] = Pbuf(c, s & 1); A.dstr4[a] = FOUT / 4;       A.coef[a] = 2.f; }
            A.xw[a] = XWcol(c, k);
        }
        switch (nact) {
            case 1: k_cle<1><<<NN, 288>>>(A); break;
            case 2: k_cle<2><<<NN, 288>>>(A); break;
            case 3: k_cle<3><<<NN, 288>>>(A); break;
            default: k_cle<4><<<NN, 288>>>(A); break;
        }
    }
}